// round 4
// baseline (speedup 1.0000x reference)
#include <cuda_runtime.h>
#include <cstdint>

#define MDIM 16384
#define NDIM 2048   // outputs
#define KDIM 2048   // inputs

#define MAXNNZ 640          // per-output row capacity (dead rows ~442, +pad)
#define TB 32               // batch rows per CTA
#define KTILE 1024          // k per pass
#define PADB 33             // padded smem row (bank-conflict-free)
#define SMX_FLOATS (KTILE * PADB)            // 33792
#define YBUF_FLOATS (8 * 32 * PADB)          // 8448
#define SMEM_BYTES ((SMX_FLOATS + YBUF_FLOATS) * 4)   // 168960

// CSR scratch (device globals: allocation-free)
__device__ uint2 g_csr[(size_t)NDIM * MAXNNZ];   // (klocal*PADB, w-bits)
__device__ int   g_mid[NDIM];                    // padded count of k<1024 entries
__device__ int   g_cnt[NDIM];                    // padded total count

// ---------------- CSR build: one warp per output row, deterministic ----------------
__global__ __launch_bounds__(256)
void prep_csr_kernel(const float* __restrict__ w, const float* __restrict__ m) {
    const int lane = threadIdx.x & 31;
    const int o = blockIdx.x * 8 + (threadIdx.x >> 5);
    const float* wr = w + (size_t)o * KDIM;
    const float* mr = m + (size_t)o * KDIM;
    uint2* out = g_csr + (size_t)o * MAXNNZ;

    int base = 0;
    int mid = 0;
    #pragma unroll 4
    for (int step = 0; step < 64; step++) {
        const int k = step * 32 + lane;
        const float v = wr[k] * mr[k];
        const bool nz = (v != 0.0f);
        const unsigned bal = __ballot_sync(0xFFFFFFFFu, nz);
        const int pos = base + __popc(bal & ((1u << lane) - 1u));
        if (nz) out[pos] = make_uint2((uint32_t)((k & 1023) * PADB), __float_as_uint(v));
        base += __popc(bal);
        if (step == 31) {
            if (base & 1) {                       // pad half0 to even length
                if (lane == 0) out[base] = make_uint2(0u, 0u);
                base++;
            }
            mid = base;
        }
    }
    if (base & 1) {                               // pad total to even length
        if (lane == 0) out[base] = make_uint2(0u, 0u);
        base++;
    }
    if (lane == 0) { g_mid[o] = mid; g_cnt[o] = base; }
}

// ---------------- SpMM pass: y[b, o] (+)= sum_{k in half} x[b,k] * w[o,k] ----------------
__global__ __launch_bounds__(256)
void spmm_kernel(const float* __restrict__ x, const float* __restrict__ bias,
                 float* __restrict__ y, int khalf) {
    extern __shared__ float sm[];
    float* x_sm = sm;                  // [KTILE][PADB]
    float* ybuf = sm + SMX_FLOATS;     // [8 warps][32 o][PADB]

    const int tid = threadIdx.x;
    const int warp = tid >> 5;
    const int lane = tid & 31;
    const int b0 = blockIdx.x * TB;
    const int kbase = khalf * KTILE;

    // ---- load x tile [TB rows][KTILE cols] transposed into smem ----
    {
        const int lb = tid >> 3;              // 0..31 batch row
        const int lc = (tid & 7) * 4;         // k offset within 32
        const float* xrow = x + (size_t)(b0 + lb) * KDIM + kbase;
        #pragma unroll
        for (int j = 0; j < 32; j++) {
            const int k = lc + j * 32;
            const float4 v = *reinterpret_cast<const float4*>(xrow + k);
            x_sm[(k + 0) * PADB + lb] = v.x;
            x_sm[(k + 1) * PADB + lb] = v.y;
            x_sm[(k + 2) * PADB + lb] = v.z;
            x_sm[(k + 3) * PADB + lb] = v.w;
        }
    }
    __syncthreads();

    float* wybuf = ybuf + warp * (32 * PADB);
    const int obase_w = warp * 256;            // 256 contiguous outputs per warp

    for (int oc = 0; oc < 8; oc++) {
        const int ob = obase_w + oc * 32;

        // compute 32 outputs, scalar accumulators, lane = batch row
        for (int oi = 0; oi < 32; oi++) {
            const int o = ob + oi;
            const int s = khalf ? g_mid[o] : 0;
            const int e = khalf ? g_cnt[o] : g_mid[o];
            const uint2* row = g_csr + (size_t)o * MAXNNZ;
            float acc0 = 0.0f, acc1 = 0.0f;
            #pragma unroll 2
            for (int j = s; j < e; j += 2) {
                const uint4 q = __ldg(reinterpret_cast<const uint4*>(row + j));
                acc0 = fmaf(x_sm[q.x + lane], __uint_as_float(q.y), acc0);
                acc1 = fmaf(x_sm[q.z + lane], __uint_as_float(q.w), acc1);
            }
            wybuf[oi * PADB + lane] = acc0 + acc1;
        }
        __syncwarp();

        // flush: lane = output, loop over batch rows -> coalesced y stores
        const float bs = khalf ? __ldg(bias + ob + lane) : 0.0f;
        #pragma unroll 4
        for (int b = 0; b < 32; b++) {
            float v = wybuf[lane * PADB + b];
            float* yp = y + (size_t)(b0 + b) * NDIM + ob + lane;
            if (khalf) v += *yp + bs;
            *yp = v;
        }
        __syncwarp();
    }
}

extern "C" void kernel_launch(void* const* d_in, const int* in_sizes, int n_in,
                              void* d_out, int out_size) {
    const float* x    = (const float*)d_in[0];
    const float* w    = (const float*)d_in[1];
    const float* bias = (const float*)d_in[2];
    const float* mask = (const float*)d_in[3];
    float* y = (float*)d_out;

    prep_csr_kernel<<<NDIM / 8, 256>>>(w, mask);

    cudaFuncSetAttribute(spmm_kernel,
                         cudaFuncAttributeMaxDynamicSharedMemorySize, SMEM_BYTES);
    spmm_kernel<<<MDIM / TB, 256, SMEM_BYTES>>>(x, bias, y, 0);
    spmm_kernel<<<MDIM / TB, 256, SMEM_BYTES>>>(x, bias, y, 1);
}

// round 5
// speedup vs baseline: 1.7247x; 1.7247x over previous
#include <cuda_runtime.h>
#include <cstdint>

#define MDIM 16384
#define NDIM 2048   // outputs
#define KDIM 2048   // inputs

#define MAXNNZ 640          // per-output row capacity (dead rows ~456 incl pad)
#define TB 32               // batch rows per CTA
#define KTILE 1024          // k per pass
#define PADB 33             // padded smem row (bank-conflict-free)
#define SMX_FLOATS (KTILE * PADB)            // 33792
#define YBUF_FLOATS (8 * 32 * PADB)          // 8448
#define SMEM_BYTES ((SMX_FLOATS + YBUF_FLOATS) * 4)   // 168960
#define NCHUNK (NDIM / 32)   // 64 output chunks of 32

// CSR scratch (device globals: allocation-free)
__device__ uint2 g_csr[(size_t)NDIM * MAXNNZ];   // (klocal*PADB, w-bits)
__device__ int   g_mid[NDIM];                    // padded end of k<1024 entries
__device__ int   g_cnt[NDIM];                    // padded total count

// ---------------- CSR build: one warp per output row, deterministic ----------------
// Each half padded with zero-entries to a multiple of 8 (enables uint4 x4 batched fetch).
__global__ __launch_bounds__(256)
void prep_csr_kernel(const float* __restrict__ w, const float* __restrict__ m) {
    const int lane = threadIdx.x & 31;
    const int o = blockIdx.x * 8 + (threadIdx.x >> 5);
    const float* wr = w + (size_t)o * KDIM;
    const float* mr = m + (size_t)o * KDIM;
    uint2* out = g_csr + (size_t)o * MAXNNZ;

    int base = 0;
    int mid = 0;
    #pragma unroll 4
    for (int step = 0; step < 64; step++) {
        const int k = step * 32 + lane;
        const float v = wr[k] * mr[k];
        const bool nz = (v != 0.0f);
        const unsigned bal = __ballot_sync(0xFFFFFFFFu, nz);
        const int pos = base + __popc(bal & ((1u << lane) - 1u));
        if (nz) out[pos] = make_uint2((uint32_t)((k & 1023) * PADB), __float_as_uint(v));
        base += __popc(bal);
        if (step == 31) {
            const int pad = (8 - (base & 7)) & 7;
            if (lane < pad) out[base + lane] = make_uint2(0u, 0u);
            base += pad;
            mid = base;
        }
    }
    {
        const int pad = (8 - (base & 7)) & 7;
        if (lane < pad) out[base + lane] = make_uint2(0u, 0u);
        base += pad;
    }
    if (lane == 0) { g_mid[o] = mid; g_cnt[o] = base; }
}

// ---------------- SpMM pass: y[b, o] (+)= sum_{k in half} x[b,k] * w[o,k] ----------------
__global__ __launch_bounds__(256)
void spmm_kernel(const float* __restrict__ x, const float* __restrict__ bias,
                 float* __restrict__ y, int khalf) {
    extern __shared__ float sm[];
    float* x_sm = sm;                  // [KTILE][PADB]
    float* ybuf = sm + SMX_FLOATS;     // [8 warps][32 o][PADB]
    __shared__ int next_chunk;

    const int tid = threadIdx.x;
    const int warp = tid >> 5;
    const int lane = tid & 31;
    const int b0 = blockIdx.x * TB;
    const int kbase = khalf * KTILE;

    if (tid == 0) next_chunk = 0;

    // ---- load x tile [TB rows][KTILE cols] transposed into smem (conflict-free) ----
    {
        const int lb = tid >> 3;              // 0..31 batch row
        const int lc = (tid & 7) * 4;         // k offset within 32
        const float* xrow = x + (size_t)(b0 + lb) * KDIM + kbase;
        #pragma unroll
        for (int j = 0; j < 32; j++) {
            const int k = lc + j * 32;
            const float4 v = *reinterpret_cast<const float4*>(xrow + k);
            x_sm[(k + 0) * PADB + lb] = v.x;
            x_sm[(k + 1) * PADB + lb] = v.y;
            x_sm[(k + 2) * PADB + lb] = v.z;
            x_sm[(k + 3) * PADB + lb] = v.w;
        }
    }
    __syncthreads();

    float* wybuf = ybuf + warp * (32 * PADB);

    // ---- warp-level work stealing over 64 chunks of 32 outputs ----
    for (;;) {
        int c;
        if (lane == 0) c = atomicAdd(&next_chunk, 1);
        c = __shfl_sync(0xFFFFFFFFu, c, 0);
        if (c >= NCHUNK) break;
        const int ob = c * 32;

        // compute 32 outputs; lane = batch row; 4 accs + MLP-4 batched CSR fetch
        for (int oi = 0; oi < 32; oi++) {
            const int o = ob + oi;
            const int s = khalf ? __ldg(g_mid + o) : 0;
            const int e = khalf ? __ldg(g_cnt + o) : __ldg(g_mid + o);
            const uint2* row = g_csr + (size_t)o * MAXNNZ;
            float a0 = 0.0f, a1 = 0.0f, a2 = 0.0f, a3 = 0.0f;
            for (int j = s; j < e; j += 8) {
                const uint4 q0 = __ldg(reinterpret_cast<const uint4*>(row + j));
                const uint4 q1 = __ldg(reinterpret_cast<const uint4*>(row + j + 2));
                const uint4 q2 = __ldg(reinterpret_cast<const uint4*>(row + j + 4));
                const uint4 q3 = __ldg(reinterpret_cast<const uint4*>(row + j + 6));
                a0 = fmaf(x_sm[q0.x + lane], __uint_as_float(q0.y), a0);
                a1 = fmaf(x_sm[q0.z + lane], __uint_as_float(q0.w), a1);
                a2 = fmaf(x_sm[q1.x + lane], __uint_as_float(q1.y), a2);
                a3 = fmaf(x_sm[q1.z + lane], __uint_as_float(q1.w), a3);
                a0 = fmaf(x_sm[q2.x + lane], __uint_as_float(q2.y), a0);
                a1 = fmaf(x_sm[q2.z + lane], __uint_as_float(q2.w), a1);
                a2 = fmaf(x_sm[q3.x + lane], __uint_as_float(q3.y), a2);
                a3 = fmaf(x_sm[q3.z + lane], __uint_as_float(q3.w), a3);
            }
            wybuf[oi * PADB + lane] = (a0 + a1) + (a2 + a3);
        }
        __syncwarp();

        // flush: lane = output, loop over batch rows -> coalesced y stores
        const float bs = khalf ? __ldg(bias + ob + lane) : 0.0f;
        #pragma unroll 4
        for (int b = 0; b < 32; b++) {
            float v = wybuf[lane * PADB + b];
            float* yp = y + (size_t)(b0 + b) * NDIM + ob + lane;
            if (khalf) v += *yp + bs;
            *yp = v;
        }
        __syncwarp();
    }
}

extern "C" void kernel_launch(void* const* d_in, const int* in_sizes, int n_in,
                              void* d_out, int out_size) {
    const float* x    = (const float*)d_in[0];
    const float* w    = (const float*)d_in[1];
    const float* bias = (const float*)d_in[2];
    const float* mask = (const float*)d_in[3];
    float* y = (float*)d_out;

    prep_csr_kernel<<<NDIM / 8, 256>>>(w, mask);

    cudaFuncSetAttribute(spmm_kernel,
                         cudaFuncAttributeMaxDynamicSharedMemorySize, SMEM_BYTES);
    spmm_kernel<<<MDIM / TB, 256, SMEM_BYTES>>>(x, bias, y, 0);
    spmm_kernel<<<MDIM / TB, 256, SMEM_BYTES>>>(x, bias, y, 1);
}

// round 7
// speedup vs baseline: 1.8065x; 1.0474x over previous
#include <cuda_runtime.h>
#include <cstdint>

#define MDIM 16384
#define NDIM 2048   // outputs
#define KDIM 2048   // inputs

#define TB 32               // batch rows per CTA
#define KTILE 1024          // k per pass
#define PADB 33             // padded smem row (bank-conflict-free)
#define SMX_FLOATS (KTILE * PADB)            // 33792
#define YBUF_FLOATS (8 * 32 * PADB)          // 8448
#define SMEM_BYTES ((SMX_FLOATS + YBUF_FLOATS) * 4)   // 168960
#define NCHUNK 64           // 64 chunks of 32 contiguous outputs
#define CHUNK_CAP 6144      // entries per chunk-half (chunk0-half ~3.8K worst case)

// Packed per-chunk weight streams (device globals: allocation-free)
__device__ uint2 g_pack[(size_t)NCHUNK * 2 * CHUNK_CAP];  // (klocal*PADB, w-bits)
__device__ int   g_hdr[NCHUNK * 2 * 33];                  // per-output segment offsets

// ---------------- prep: one CTA per chunk, builds packed streams ----------------
__global__ __launch_bounds__(256)
void prep_pack_kernel(const float* __restrict__ w, const float* __restrict__ m) {
    __shared__ int s_cnt[2][32];     // padded-to-8 counts
    __shared__ int s_start[2][33];
    const int chunk = blockIdx.x;
    const int tid = threadIdx.x;
    const int warp = tid >> 5;
    const int lane = tid & 31;
    const unsigned lt = (1u << lane) - 1u;

    // phase 1: count nnz per output per half, pad to multiple of 8
    #pragma unroll 1
    for (int r = 0; r < 4; r++) {
        const int oi = warp * 4 + r;
        const int o = chunk * 32 + oi;
        const float* wr = w + (size_t)o * KDIM;
        const float* mr = m + (size_t)o * KDIM;
        int c0 = 0, c1 = 0;
        for (int step = 0; step < 64; step++) {
            const int k = step * 32 + lane;
            const bool nz = (wr[k] * mr[k]) != 0.0f;
            const int n = __popc(__ballot_sync(0xFFFFFFFFu, nz));
            if (step < 32) c0 += n; else c1 += n;
        }
        if (lane == 0) {
            s_cnt[0][oi] = (c0 + 7) & ~7;
            s_cnt[1][oi] = (c1 + 7) & ~7;
        }
    }
    __syncthreads();

    // phase 2: exclusive scan + write header
    if (tid == 0) {
        for (int h = 0; h < 2; h++) {
            int acc = 0;
            for (int i = 0; i < 32; i++) { s_start[h][i] = acc; acc += s_cnt[h][i]; }
            s_start[h][32] = acc;
            for (int i = 0; i < 33; i++)
                g_hdr[(chunk * 2 + h) * 33 + i] = s_start[h][i];
        }
    }
    __syncthreads();

    // phase 3: fill streams (same value computation -> deterministic)
    #pragma unroll 1
    for (int r = 0; r < 4; r++) {
        const int oi = warp * 4 + r;
        const int o = chunk * 32 + oi;
        const float* wr = w + (size_t)o * KDIM;
        const float* mr = m + (size_t)o * KDIM;
        uint2* b0 = g_pack + (size_t)(chunk * 2 + 0) * CHUNK_CAP;
        uint2* b1 = g_pack + (size_t)(chunk * 2 + 1) * CHUNK_CAP;
        int p0 = s_start[0][oi];
        int p1 = s_start[1][oi];
        for (int step = 0; step < 64; step++) {
            const int k = step * 32 + lane;
            const float v = wr[k] * mr[k];
            const bool nz = (v != 0.0f);
            const unsigned bal = __ballot_sync(0xFFFFFFFFu, nz);
            uint2* dst = (step < 32) ? b0 : b1;
            const int p = (step < 32) ? p0 : p1;
            if (nz) dst[p + __popc(bal & lt)] =
                make_uint2((uint32_t)((k & 1023) * PADB), __float_as_uint(v));
            if (step < 32) p0 += __popc(bal); else p1 += __popc(bal);
        }
        // zero-pad segments to their padded ends
        const int e0 = s_start[0][oi] + s_cnt[0][oi];
        const int e1 = s_start[1][oi] + s_cnt[1][oi];
        for (int j = p0 + lane; j < e0; j += 32) b0[j] = make_uint2(0u, 0u);
        for (int j = p1 + lane; j < e1; j += 32) b1[j] = make_uint2(0u, 0u);
    }
}

// ---------------- SpMM pass: y[b, o] (+)= sum_{k in half} x[b,k] * w[o,k] ----------------
__global__ __launch_bounds__(256)
void spmm_kernel(const float* __restrict__ x, const float* __restrict__ bias,
                 float* __restrict__ y, int khalf) {
    extern __shared__ float sm[];
    float* x_sm = sm;                  // [KTILE][PADB]
    float* ybuf = sm + SMX_FLOATS;     // [8 warps][32 o][PADB]
    __shared__ int next_chunk;

    const int tid = threadIdx.x;
    const int warp = tid >> 5;
    const int lane = tid & 31;
    const int b0 = blockIdx.x * TB;
    const int kbase = khalf * KTILE;

    if (tid == 0) next_chunk = 0;

    // ---- load x tile [TB rows][KTILE cols] transposed into smem (conflict-free) ----
    {
        const int lb = tid >> 3;              // 0..31 batch row
        const int lc = (tid & 7) * 4;         // k offset within 32
        const float* xrow = x + (size_t)(b0 + lb) * KDIM + kbase;
        #pragma unroll
        for (int j = 0; j < 32; j++) {
            const int k = lc + j * 32;
            const float4 v = *reinterpret_cast<const float4*>(xrow + k);
            x_sm[(k + 0) * PADB + lb] = v.x;
            x_sm[(k + 1) * PADB + lb] = v.y;
            x_sm[(k + 2) * PADB + lb] = v.z;
            x_sm[(k + 3) * PADB + lb] = v.w;
        }
    }
    __syncthreads();

    float* wybuf = ybuf + warp * (32 * PADB);

    // ---- warp-level work stealing over 64 chunks of 32 outputs ----
    for (;;) {
        int c;
        if (lane == 0) c = atomicAdd(&next_chunk, 1);
        c = __shfl_sync(0xFFFFFFFFu, c, 0);
        if (c >= NCHUNK) break;
        const int ob = c * 32;

        // one coalesced header load per chunk; bounds distributed via shfl
        const int* hb = g_hdr + (c * 2 + khalf) * 33;
        const int hv = __ldg(hb + lane);          // offsets [0..31]
        const int tot = __ldg(hb + 32);
        const uint2* stream = g_pack + (size_t)(c * 2 + khalf) * CHUNK_CAP;

        // compute 32 outputs; lane = batch row; segment bounds already in regs
        for (int oi = 0; oi < 32; oi++) {
            const int s = __shfl_sync(0xFFFFFFFFu, hv, oi);
            const int e = (oi < 31) ? __shfl_sync(0xFFFFFFFFu, hv, oi + 1) : tot;
            float a0 = 0.0f, a1 = 0.0f, a2 = 0.0f, a3 = 0.0f;
            for (int j = s; j < e; j += 8) {
                const uint4 q0 = __ldg(reinterpret_cast<const uint4*>(stream + j));
                const uint4 q1 = __ldg(reinterpret_cast<const uint4*>(stream + j + 2));
                const uint4 q2 = __ldg(reinterpret_cast<const uint4*>(stream + j + 4));
                const uint4 q3 = __ldg(reinterpret_cast<const uint4*>(stream + j + 6));
                a0 = fmaf(x_sm[q0.x + lane], __uint_as_float(q0.y), a0);
                a1 = fmaf(x_sm[q0.z + lane], __uint_as_float(q0.w), a1);
                a2 = fmaf(x_sm[q1.x + lane], __uint_as_float(q1.y), a2);
                a3 = fmaf(x_sm[q1.z + lane], __uint_as_float(q1.w), a3);
                a0 = fmaf(x_sm[q2.x + lane], __uint_as_float(q2.y), a0);
                a1 = fmaf(x_sm[q2.z + lane], __uint_as_float(q2.w), a1);
                a2 = fmaf(x_sm[q3.x + lane], __uint_as_float(q3.y), a2);
                a3 = fmaf(x_sm[q3.z + lane], __uint_as_float(q3.w), a3);
            }
            wybuf[oi * PADB + lane] = (a0 + a1) + (a2 + a3);
        }
        __syncwarp();

        // flush: lane = output, loop over batch rows -> coalesced y stores
        const float bs = khalf ? __ldg(bias + ob + lane) : 0.0f;
        #pragma unroll 4
        for (int b = 0; b < 32; b++) {
            float v = wybuf[lane * PADB + b];
            float* yp = y + (size_t)(b0 + b) * NDIM + ob + lane;
            if (khalf) v += *yp + bs;
            *yp = v;
        }
        __syncwarp();
    }
}

extern "C" void kernel_launch(void* const* d_in, const int* in_sizes, int n_in,
                              void* d_out, int out_size) {
    const float* x    = (const float*)d_in[0];
    const float* w    = (const float*)d_in[1];
    const float* bias = (const float*)d_in[2];
    const float* mask = (const float*)d_in[3];
    float* y = (float*)d_out;

    prep_pack_kernel<<<NCHUNK, 256>>>(w, mask);

    cudaFuncSetAttribute(spmm_kernel,
                         cudaFuncAttributeMaxDynamicSharedMemorySize, SMEM_BYTES);
    spmm_kernel<<<MDIM / TB, 256, SMEM_BYTES>>>(x, bias, y, 0);
    spmm_kernel<<<MDIM / TB, 256, SMEM_BYTES>>>(x, bias, y, 1);
}

// round 9
// speedup vs baseline: 2.8741x; 1.5910x over previous
#include <cuda_runtime.h>
#include <cstdint>

#define MDIM 16384
#define NDIM 2048
#define KDIM 2048

#define TB 32
#define KTILE 1024
#define PADB 33
#define NCHUNK 64
#define CAP_E 4608                       // max entries per chunk-half (chunk0 ~4100 worst)
#define BLOCK_STRIDE 37120               // 144B header + 4608*8B entries, 128B-aligned

// smem layout (bytes)
#define X_BYTES (KTILE * PADB * 4)       // 135168
#define YB_OFF  X_BYTES                  // 135168
#define YB_BYTES (32 * PADB * 4)         // 4224
#define SZ_OFF  (YB_OFF + YB_BYTES)      // 139392
#define SB_OFF  (SZ_OFF + 256)           // 139648 (16B aligned)
#define SMEM_BYTES (SB_OFF + 2 * BLOCK_STRIDE)   // 213888 (< 227KB)

// packed chunk streams (device globals: allocation-free)
__device__ __align__(16) unsigned char g_pack[(size_t)NCHUNK * 2 * BLOCK_STRIDE];
__device__ int g_csize[NCHUNK * 2];      // bytes to copy per (chunk, half)

__device__ __forceinline__ uint32_t smem_u32(const void* p) {
    uint32_t a;
    asm("{ .reg .u64 t; cvta.to.shared.u64 t, %1; cvt.u32.u64 %0, t; }" : "=r"(a) : "l"(p));
    return a;
}
#define CP_ASYNC16(dst, src) \
    asm volatile("cp.async.cg.shared.global [%0], [%1], 16;\n" :: "r"(dst), "l"(src))
#define CP_COMMIT() asm volatile("cp.async.commit_group;\n" ::: "memory")
#define CP_WAIT1()  asm volatile("cp.async.wait_group 1;\n" ::: "memory")
#define CP_WAIT0()  asm volatile("cp.async.wait_group 0;\n" ::: "memory")

// ---------------- prep: one CTA per chunk (32 contiguous outputs) ----------------
__global__ __launch_bounds__(512)
void prep_pack_kernel(const float* __restrict__ w, const float* __restrict__ m) {
    __shared__ int s_cnt[2][32];     // per-output padded-to-8 counts
    __shared__ int s_start[2][33];
    const int chunk = blockIdx.x;
    const int tid = threadIdx.x;
    const int warp = tid >> 5;       // 0..15
    const int lane = tid & 31;
    const unsigned lt = (1u << lane) - 1u;

    // phase 1: count nnz per output per half, pad to multiple of 8
    #pragma unroll 1
    for (int r = 0; r < 2; r++) {
        const int oi = warp * 2 + r;
        const int o = chunk * 32 + oi;
        const float* wr = w + (size_t)o * KDIM;
        const float* mr = m + (size_t)o * KDIM;
        int c0 = 0, c1 = 0;
        for (int step = 0; step < 64; step++) {
            const int k = step * 32 + lane;
            const bool nz = (wr[k] * mr[k]) != 0.0f;
            const int n = __popc(__ballot_sync(0xFFFFFFFFu, nz));
            if (step < 32) c0 += n; else c1 += n;
        }
        if (lane == 0) {
            s_cnt[0][oi] = (c0 + 7) & ~7;
            s_cnt[1][oi] = (c1 + 7) & ~7;
        }
    }
    __syncthreads();

    // phase 2: scan, write headers + copy sizes
    if (tid == 0) {
        for (int h = 0; h < 2; h++) {
            int acc = 0;
            int* hdr = (int*)(g_pack + (size_t)(chunk * 2 + h) * BLOCK_STRIDE);
            for (int i = 0; i < 32; i++) { s_start[h][i] = acc; hdr[i] = acc; acc += s_cnt[h][i]; }
            s_start[h][32] = acc;
            hdr[32] = acc;
            g_csize[chunk * 2 + h] = 144 + acc * 8;
        }
    }
    __syncthreads();

    // phase 3: fill entries (identical value computation -> deterministic)
    #pragma unroll 1
    for (int r = 0; r < 2; r++) {
        const int oi = warp * 2 + r;
        const int o = chunk * 32 + oi;
        const float* wr = w + (size_t)o * KDIM;
        const float* mr = m + (size_t)o * KDIM;
        uint2* b0 = (uint2*)(g_pack + (size_t)(chunk * 2 + 0) * BLOCK_STRIDE + 144);
        uint2* b1 = (uint2*)(g_pack + (size_t)(chunk * 2 + 1) * BLOCK_STRIDE + 144);
        int p0 = s_start[0][oi];
        int p1 = s_start[1][oi];
        for (int step = 0; step < 64; step++) {
            const int k = step * 32 + lane;
            const float v = wr[k] * mr[k];
            const bool nz = (v != 0.0f);
            const unsigned bal = __ballot_sync(0xFFFFFFFFu, nz);
            uint2* dst = (step < 32) ? b0 : b1;
            const int p = (step < 32) ? p0 : p1;
            if (nz) dst[p + __popc(bal & lt)] =
                make_uint2((uint32_t)((k & 1023) * PADB), __float_as_uint(v));
            if (step < 32) p0 += __popc(bal); else p1 += __popc(bal);
        }
        const int e0 = s_start[0][oi] + s_cnt[0][oi];
        const int e1 = s_start[1][oi] + s_cnt[1][oi];
        for (int j = p0 + lane; j < e0; j += 32) b0[j] = make_uint2(0u, 0u);
        for (int j = p1 + lane; j < e1; j += 32) b1[j] = make_uint2(0u, 0u);
    }
}

// ---------------- SpMM pass: all chunks per CTA, smem-staged streams ----------------
__global__ __launch_bounds__(512)
void spmm_kernel(const float* __restrict__ x, const float* __restrict__ bias,
                 float* __restrict__ y, int khalf) {
    extern __shared__ __align__(16) unsigned char smc[];
    float* x_sm = (float*)smc;                       // [KTILE][PADB]
    float* ybuf = (float*)(smc + YB_OFF);            // [32 o][PADB]
    int* s_sz   = (int*)(smc + SZ_OFF);              // [64] copy bytes this half
    const uint32_t sbuf_u32 = smem_u32(smc + SB_OFF);

    const int tid = threadIdx.x;
    const int warp = tid >> 5;
    const int lane = tid & 31;
    const int b0 = blockIdx.x * TB;
    const int kbase = khalf * KTILE;

    if (tid < NCHUNK) s_sz[tid] = g_csize[tid * 2 + khalf];

    // ---- x tile [TB rows][KTILE k] transposed into smem ----
    {
        const int lb = tid >> 4;               // 0..31 batch row
        const int lc = (tid & 15) * 4;         // k offset within 64
        const float* xr = x + (size_t)(b0 + lb) * KDIM + kbase;
        #pragma unroll
        for (int j = 0; j < 16; j++) {
            const int k = lc + j * 64;
            const float4 v = *reinterpret_cast<const float4*>(xr + k);
            x_sm[(k + 0) * PADB + lb] = v.x;
            x_sm[(k + 1) * PADB + lb] = v.y;
            x_sm[(k + 2) * PADB + lb] = v.z;
            x_sm[(k + 3) * PADB + lb] = v.w;
        }
    }
    __syncthreads();    // s_sz + x_sm visible

    auto issue_copy = [&](int c) {
        const int bytes = s_sz[c];
        const unsigned char* src = g_pack + (size_t)(c * 2 + khalf) * BLOCK_STRIDE;
        const uint32_t dst = sbuf_u32 + (uint32_t)(c & 1) * BLOCK_STRIDE;
        for (int off = tid * 16; off < bytes; off += 512 * 16)
            CP_ASYNC16(dst + off, src + off);
        CP_COMMIT();
    };

    issue_copy(0);

    for (int c = 0; c < NCHUNK; c++) {
        if (c + 1 < NCHUNK) { issue_copy(c + 1); CP_WAIT1(); }
        else                { CP_WAIT0(); }
        __syncthreads();    // sbuf[c&1] ready; ybuf flush of c-1 done everywhere

        // ---- compute chunk c entirely from smem ----
        const unsigned char* sb = smc + SB_OFF + (size_t)(c & 1) * BLOCK_STRIDE;
        const int* hdr = (const int*)sb;
        const uint4* ep = (const uint4*)(sb + 144);
        #pragma unroll
        for (int t = 0; t < 2; t++) {
            const int oi = warp + t * 16;
            const int s = hdr[oi];
            const int e = hdr[oi + 1];
            float a0 = 0.0f, a1 = 0.0f, a2 = 0.0f, a3 = 0.0f;
            for (int j = s; j < e; j += 8) {
                const uint4 q0 = ep[(j >> 1) + 0];
                const uint4 q1 = ep[(j >> 1) + 1];
                const uint4 q2 = ep[(j >> 1) + 2];
                const uint4 q3 = ep[(j >> 1) + 3];
                a0 = fmaf(x_sm[q0.x + lane], __uint_as_float(q0.y), a0);
                a1 = fmaf(x_sm[q0.z + lane], __uint_as_float(q0.w), a1);
                a2 = fmaf(x_sm[q1.x + lane], __uint_as_float(q1.y), a2);
                a3 = fmaf(x_sm[q1.z + lane], __uint_as_float(q1.w), a3);
                a0 = fmaf(x_sm[q2.x + lane], __uint_as_float(q2.y), a0);
                a1 = fmaf(x_sm[q2.z + lane], __uint_as_float(q2.w), a1);
                a2 = fmaf(x_sm[q3.x + lane], __uint_as_float(q3.y), a2);
                a3 = fmaf(x_sm[q3.z + lane], __uint_as_float(q3.w), a3);
            }
            ybuf[oi * PADB + lane] = (a0 + a1) + (a2 + a3);
        }
        __syncthreads();    // ybuf complete; sbuf[c&1] reads done

        // ---- flush: coalesced y stores (lane = output) ----
        const int o = tid & 31;
        const int brow = tid >> 5;         // 0..15
        const int ob = c * 32;
        const float bsv = khalf ? __ldg(bias + ob + o) : 0.0f;
        #pragma unroll
        for (int t = 0; t < 2; t++) {
            const int b = brow + t * 16;
            float v = ybuf[o * PADB + b];
            float* yp = y + (size_t)(b0 + b) * NDIM + ob + o;
            if (khalf) v += *yp + bsv;
            *yp = v;
        }
    }
}

extern "C" void kernel_launch(void* const* d_in, const int* in_sizes, int n_in,
                              void* d_out, int out_size) {
    const float* x    = (const float*)d_in[0];
    const float* w    = (const float*)d_in[1];
    const float* bias = (const float*)d_in[2];
    const float* mask = (const float*)d_in[3];
    float* y = (float*)d_out;

    prep_pack_kernel<<<NCHUNK, 512>>>(w, mask);

    cudaFuncSetAttribute(spmm_kernel,
                         cudaFuncAttributeMaxDynamicSharedMemorySize, SMEM_BYTES);
    spmm_kernel<<<MDIM / TB, 512, SMEM_BYTES>>>(x, bias, y, 0);
    spmm_kernel<<<MDIM / TB, 512, SMEM_BYTES>>>(x, bias, y, 1);
}

// round 10
// speedup vs baseline: 4.9549x; 1.7240x over previous
#include <cuda_runtime.h>
#include <cuda_fp16.h>
#include <cstdint>

#define MDIM 16384
#define NDIM 2048
#define KDIM 2048

#define BM 128
#define BN 128
#define BK 32
#define LDSX 40                         // padded smem row stride (elements)
#define TILE_BYTES (BM * LDSX * 2)      // 10240 B per tile
#define STAGE_BYTES (3 * TILE_BYTES)    // A, B_hi, B_lo
#define NSTAGE 3
#define SMEM_TOTAL (NSTAGE * STAGE_BYTES)   // 92160 B

#define A_OFF  0
#define BH_OFF TILE_BYTES
#define BL_OFF (2 * TILE_BYTES)

// fp16 scratch (device globals: allocation-free per harness rules)
__device__ __half g_xh[(size_t)MDIM * KDIM];
__device__ __half g_wh[(size_t)NDIM * KDIM];
__device__ __half g_wl[(size_t)NDIM * KDIM];

__global__ void split_x_kernel(const float4* __restrict__ x, int n4) {
    int i = blockIdx.x * blockDim.x + threadIdx.x;
    if (i >= n4) return;
    float4 v = x[i];
    __half2* ph = reinterpret_cast<__half2*>(g_xh);
    __half2 a, b;
    a.x = __float2half_rn(v.x); a.y = __float2half_rn(v.y);
    b.x = __float2half_rn(v.z); b.y = __float2half_rn(v.w);
    ph[2 * i] = a; ph[2 * i + 1] = b;
}

__device__ __forceinline__ void split1(float p, __half& h, __half& l) {
    h = __float2half_rn(p);
    l = __float2half_rn(p - __half2float(h));
}

__global__ void split_w_kernel(const float4* __restrict__ w,
                               const float4* __restrict__ m, int n4) {
    int i = blockIdx.x * blockDim.x + threadIdx.x;
    if (i >= n4) return;
    float4 wv = w[i];
    float4 mv = m[i];
    float p0 = wv.x * mv.x, p1 = wv.y * mv.y, p2 = wv.z * mv.z, p3 = wv.w * mv.w;
    __half h0, h1, h2, h3, l0, l1, l2, l3;
    split1(p0, h0, l0); split1(p1, h1, l1);
    split1(p2, h2, l2); split1(p3, h3, l3);
    __half2* ph = reinterpret_cast<__half2*>(g_wh);
    __half2* pl = reinterpret_cast<__half2*>(g_wl);
    __half2 a, b;
    a.x = h0; a.y = h1; b.x = h2; b.y = h3;
    ph[2 * i] = a; ph[2 * i + 1] = b;
    a.x = l0; a.y = l1; b.x = l2; b.y = l3;
    pl[2 * i] = a; pl[2 * i + 1] = b;
}

#define CP_ASYNC16(dst_u32, src_ptr) \
    asm volatile("cp.async.cg.shared.global [%0], [%1], 16;\n" :: "r"(dst_u32), "l"(src_ptr))
#define CP_COMMIT() asm volatile("cp.async.commit_group;\n" ::: "memory")
#define CP_WAIT1()  asm volatile("cp.async.wait_group 1;\n" ::: "memory")

#define LDSM_X4(r0, r1, r2, r3, addr) \
    asm volatile("ldmatrix.sync.aligned.m8n8.x4.shared.b16 {%0,%1,%2,%3}, [%4];" \
                 : "=r"(r0), "=r"(r1), "=r"(r2), "=r"(r3) : "r"(addr))

#define MMA16816(d, a, b0, b1) \
    asm volatile("mma.sync.aligned.m16n8k16.row.col.f32.f16.f16.f32 " \
                 "{%0,%1,%2,%3}, {%4,%5,%6,%7}, {%8,%9}, {%0,%1,%2,%3};" \
                 : "+f"(d[0]), "+f"(d[1]), "+f"(d[2]), "+f"(d[3]) \
                 : "r"(a[0]), "r"(a[1]), "r"(a[2]), "r"(a[3]), "r"(b0), "r"(b1))

__global__ __launch_bounds__(256)
void gemm_fp16x2_kernel(float* __restrict__ out, const float* __restrict__ bias) {
    extern __shared__ __align__(16) unsigned char smem_raw[];
    const uint32_t smem_base = (uint32_t)__cvta_generic_to_shared(smem_raw);

    const int tid = threadIdx.x;
    const int lane = tid & 31;
    const int warp = tid >> 5;
    const int wm0 = (warp >> 2) * 64;   // 2 warp rows * 64
    const int wn0 = (warp & 3) * 32;    // 4 warp cols * 32
    const int gm0 = blockIdx.y * BM;
    const int gn0 = blockIdx.x * BN;

    float acc[4][4][4];
    #pragma unroll
    for (int i = 0; i < 4; i++)
        #pragma unroll
        for (int j = 0; j < 4; j++)
            #pragma unroll
            for (int r = 0; r < 4; r++)
                acc[i][j][r] = 0.0f;

    // ---- smem fill: 128 rows x 32 cols fp16, 4 chunks of 8 elems per row ----
    const int fr = tid >> 2;            // 0..63, two passes of 64 rows
    const int fc = (tid & 3) * 8;       // element offset of 16B chunk

    auto load_stage = [&](int kt, int s) {
        const int k0 = kt * BK;
        const uint32_t sbase = smem_base + (uint32_t)s * STAGE_BYTES;
        #pragma unroll
        for (int p = 0; p < 2; p++) {
            const int row = fr + p * 64;
            const uint32_t d = sbase + (uint32_t)(row * LDSX + fc) * 2;
            const size_t aoff = (size_t)(gm0 + row) * KDIM + k0 + fc;
            const size_t boff = (size_t)(gn0 + row) * KDIM + k0 + fc;
            CP_ASYNC16(d + A_OFF,  g_xh + aoff);
            CP_ASYNC16(d + BH_OFF, g_wh + boff);
            CP_ASYNC16(d + BL_OFF, g_wl + boff);
        }
        CP_COMMIT();
    };

    // ldmatrix addressing (rows within tile, col selectors per lane group)
    const int a_row = wm0 + (lane & 15);
    const int a_csel = ((lane >> 4) << 3);
    const int b_row = wn0 + (lane & 7) + ((lane >> 4) << 3);
    const int b_csel = (((lane >> 3) & 1) << 3);

    load_stage(0, 0);
    load_stage(1, 1);

    const int KT = KDIM / BK;   // 64
    int s_cur = 0, s_nxt = 2;
    for (int kt = 0; kt < KT; kt++) {
        CP_WAIT1();
        __syncthreads();
        if (kt + 2 < KT) load_stage(kt + 2, s_nxt);
        else             CP_COMMIT();           // keep group count in lockstep
        s_nxt = s_cur;                          // buffer freed after this compute
        const uint32_t sb = smem_base + (uint32_t)s_cur * STAGE_BYTES;
        s_cur = (s_cur + 1 == NSTAGE) ? 0 : s_cur + 1;

        #pragma unroll
        for (int kk = 0; kk < 2; kk++) {
            const int k0 = kk * 16;
            uint32_t af[4][4];
            #pragma unroll
            for (int im = 0; im < 4; im++) {
                const uint32_t addr =
                    sb + A_OFF + (uint32_t)(((a_row + im * 16) * LDSX) + k0 + a_csel) * 2;
                LDSM_X4(af[im][0], af[im][1], af[im][2], af[im][3], addr);
            }
            uint32_t bh[2][4], bl[2][4];
            #pragma unroll
            for (int ib = 0; ib < 2; ib++) {
                const uint32_t addr =
                    sb + BH_OFF + (uint32_t)(((b_row + ib * 16) * LDSX) + k0 + b_csel) * 2;
                LDSM_X4(bh[ib][0], bh[ib][1], bh[ib][2], bh[ib][3], addr);
                LDSM_X4(bl[ib][0], bl[ib][1], bl[ib][2], bl[ib][3],
                        addr + (BL_OFF - BH_OFF));
            }
            #pragma unroll
            for (int im = 0; im < 4; im++) {
                #pragma unroll
                for (int in = 0; in < 4; in++) {
                    const int g = in >> 1;
                    const int o = (in & 1) * 2;
                    MMA16816(acc[im][in], af[im], bh[g][o], bh[g][o + 1]);
                    MMA16816(acc[im][in], af[im], bl[g][o], bl[g][o + 1]);
                }
            }
        }
    }

    // ---- epilogue ----
    #pragma unroll
    for (int im = 0; im < 4; im++) {
        #pragma unroll
        for (int in = 0; in < 4; in++) {
            const int row = gm0 + wm0 + im * 16 + (lane >> 2);
            const int col = gn0 + wn0 + in * 8 + ((lane & 3) << 1);
            const float b0 = bias[col];
            const float b1 = bias[col + 1];
            float2 v0 = make_float2(acc[im][in][0] + b0, acc[im][in][1] + b1);
            float2 v1 = make_float2(acc[im][in][2] + b0, acc[im][in][3] + b1);
            *reinterpret_cast<float2*>(out + (size_t)row * NDIM + col) = v0;
            *reinterpret_cast<float2*>(out + (size_t)(row + 8) * NDIM + col) = v1;
        }
    }
}

extern "C" void kernel_launch(void* const* d_in, const int* in_sizes, int n_in,
                              void* d_out, int out_size) {
    const float* x    = (const float*)d_in[0];
    const float* w    = (const float*)d_in[1];
    const float* bias = (const float*)d_in[2];
    const float* mask = (const float*)d_in[3];

    const int nx4 = (MDIM * KDIM) / 4;   // 8388608
    const int nw4 = (NDIM * KDIM) / 4;   // 1048576
    split_x_kernel<<<(nx4 + 255) / 256, 256>>>((const float4*)x, nx4);
    split_w_kernel<<<(nw4 + 255) / 256, 256>>>((const float4*)w, (const float4*)mask, nw4);

    cudaFuncSetAttribute(gemm_fp16x2_kernel,
                         cudaFuncAttributeMaxDynamicSharedMemorySize, SMEM_TOTAL);
    dim3 grid(NDIM / BN, MDIM / BM);   // (16, 128)
    gemm_fp16x2_kernel<<<grid, 256, SMEM_TOTAL>>>((float*)d_out, bias);
}

// round 12
// speedup vs baseline: 9.0495x; 1.8264x over previous
#include <cuda_runtime.h>
#include <cuda_fp16.h>
#include <cstdint>

#define MDIM 16384
#define NDIM 2048
#define KDIM 2048

#define BM 128
#define BN 128
#define BK 32
#define LDSX 40                         // padded smem row stride (elements)
#define TILE_BYTES (BM * LDSX * 2)      // 10240 B per tile
#define STAGE_BYTES (2 * TILE_BYTES)    // A, B
#define NSTAGE 4
#define SMEM_TOTAL (NSTAGE * STAGE_BYTES)   // 81920 B -> 2 CTAs/SM

#define A_OFF  0
#define B_OFF  TILE_BYTES

// fp16 scratch (device globals: allocation-free per harness rules)
__device__ __half g_xh[(size_t)MDIM * KDIM];
__device__ __half g_wh[(size_t)NDIM * KDIM];

__global__ void split_x_kernel(const float4* __restrict__ x, int n4) {
    int i = blockIdx.x * blockDim.x + threadIdx.x;
    if (i >= n4) return;
    float4 v = x[i];
    __half2* ph = reinterpret_cast<__half2*>(g_xh);
    __half2 a, b;
    a.x = __float2half_rn(v.x); a.y = __float2half_rn(v.y);
    b.x = __float2half_rn(v.z); b.y = __float2half_rn(v.w);
    ph[2 * i] = a; ph[2 * i + 1] = b;
}

__global__ void split_w_kernel(const float4* __restrict__ w,
                               const float4* __restrict__ m, int n4) {
    int i = blockIdx.x * blockDim.x + threadIdx.x;
    if (i >= n4) return;
    float4 wv = w[i];
    float4 mv = m[i];
    __half2* ph = reinterpret_cast<__half2*>(g_wh);
    __half2 a, b;
    a.x = __float2half_rn(wv.x * mv.x); a.y = __float2half_rn(wv.y * mv.y);
    b.x = __float2half_rn(wv.z * mv.z); b.y = __float2half_rn(wv.w * mv.w);
    ph[2 * i] = a; ph[2 * i + 1] = b;
}

#define CP_ASYNC16(dst_u32, src_ptr) \
    asm volatile("cp.async.cg.shared.global [%0], [%1], 16;\n" :: "r"(dst_u32), "l"(src_ptr))
#define CP_COMMIT() asm volatile("cp.async.commit_group;\n" ::: "memory")
#define CP_WAIT2()  asm volatile("cp.async.wait_group 2;\n" ::: "memory")

#define LDSM_X4(r0, r1, r2, r3, addr) \
    asm volatile("ldmatrix.sync.aligned.m8n8.x4.shared.b16 {%0,%1,%2,%3}, [%4];" \
                 : "=r"(r0), "=r"(r1), "=r"(r2), "=r"(r3) : "r"(addr))

#define MMA16816(d, a, b0, b1) \
    asm volatile("mma.sync.aligned.m16n8k16.row.col.f32.f16.f16.f32 " \
                 "{%0,%1,%2,%3}, {%4,%5,%6,%7}, {%8,%9}, {%0,%1,%2,%3};" \
                 : "+f"(d[0]), "+f"(d[1]), "+f"(d[2]), "+f"(d[3]) \
                 : "r"(a[0]), "r"(a[1]), "r"(a[2]), "r"(a[3]), "r"(b0), "r"(b1))

__global__ __launch_bounds__(256, 2)
void gemm_fp16_kernel(float* __restrict__ out, const float* __restrict__ bias) {
    extern __shared__ __align__(16) unsigned char smem_raw[];
    const uint32_t smem_base = (uint32_t)__cvta_generic_to_shared(smem_raw);

    const int tid = threadIdx.x;
    const int lane = tid & 31;
    const int warp = tid >> 5;
    const int wm0 = (warp >> 2) * 64;   // 2 warp rows * 64
    const int wn0 = (warp & 3) * 32;    // 4 warp cols * 32
    const int gm0 = blockIdx.y * BM;
    const int gn0 = blockIdx.x * BN;

    float acc[4][4][4];
    #pragma unroll
    for (int i = 0; i < 4; i++)
        #pragma unroll
        for (int j = 0; j < 4; j++)
            #pragma unroll
            for (int r = 0; r < 4; r++)
                acc[i][j][r] = 0.0f;

    // ---- smem fill: 128 rows x 32 cols fp16, 4 chunks of 8 elems per row ----
    const int fr = tid >> 2;            // 0..63, two passes of 64 rows
    const int fc = (tid & 3) * 8;       // element offset of 16B chunk

    auto load_stage = [&](int kt, int s) {
        const int k0 = kt * BK;
        const uint32_t sbase = smem_base + (uint32_t)s * STAGE_BYTES;
        #pragma unroll
        for (int p = 0; p < 2; p++) {
            const int row = fr + p * 64;
            const uint32_t d = sbase + (uint32_t)(row * LDSX + fc) * 2;
            const size_t aoff = (size_t)(gm0 + row) * KDIM + k0 + fc;
            const size_t boff = (size_t)(gn0 + row) * KDIM + k0 + fc;
            CP_ASYNC16(d + A_OFF, g_xh + aoff);
            CP_ASYNC16(d + B_OFF, g_wh + boff);
        }
        CP_COMMIT();
    };

    // ldmatrix addressing (rows within tile, col selectors per lane group)
    const int a_row = wm0 + (lane & 15);
    const int a_csel = ((lane >> 4) << 3);
    const int b_row = wn0 + (lane & 7) + ((lane >> 4) << 3);
    const int b_csel = (((lane >> 3) & 1) << 3);

    load_stage(0, 0);
    load_stage(1, 1);
    load_stage(2, 2);

    const int KT = KDIM / BK;   // 64
    for (int kt = 0; kt < KT; kt++) {
        CP_WAIT2();             // 3 groups in flight -> stage kt complete
        __syncthreads();
        if (kt + 3 < KT) load_stage(kt + 3, (kt + 3) & 3);
        else             CP_COMMIT();           // keep group count in lockstep

        const uint32_t sb = smem_base + (uint32_t)(kt & 3) * STAGE_BYTES;

        #pragma unroll
        for (int kk = 0; kk < 2; kk++) {
            const int k0 = kk * 16;
            uint32_t af[4][4];
            #pragma unroll
            for (int im = 0; im < 4; im++) {
                const uint32_t addr =
                    sb + A_OFF + (uint32_t)(((a_row + im * 16) * LDSX) + k0 + a_csel) * 2;
                LDSM_X4(af[im][0], af[im][1], af[im][2], af[im][3], addr);
            }
            uint32_t bh[2][4];
            #pragma unroll
            for (int ib = 0; ib < 2; ib++) {
                const uint32_t addr =
                    sb + B_OFF + (uint32_t)(((b_row + ib * 16) * LDSX) + k0 + b_csel) * 2;
                LDSM_X4(bh[ib][0], bh[ib][1], bh[ib][2], bh[ib][3], addr);
            }
            #pragma unroll
            for (int im = 0; im < 4; im++) {
                #pragma unroll
                for (int in = 0; in < 4; in++) {
                    const int g = in >> 1;
                    const int o = (in & 1) * 2;
                    MMA16816(acc[im][in], af[im], bh[g][o], bh[g][o + 1]);
                }
            }
        }
    }

    // ---- epilogue ----
    #pragma unroll
    for (int im = 0; im < 4; im++) {
        #pragma unroll
        for (int in = 0; in < 4; in++) {
            const int row = gm0 + wm0 + im * 16 + (lane >> 2);
            const int col = gn0 + wn0 + in * 8 + ((lane & 3) << 1);
            const float b0 = bias[col];
            const float b1 = bias[col + 1];
            float2 v0 = make_float2(acc[im][in][0] + b0, acc[im][in][1] + b1);
            float2 v1 = make_float2(acc[im][in][2] + b0, acc[im][in][3] + b1);
            *reinterpret_cast<float2*>(out + (size_t)row * NDIM + col) = v0;
            *reinterpret_cast<float2*>(out + (size_t)(row + 8) * NDIM + col) = v1;
        }
    }
}

extern "C" void kernel_launch(void* const* d_in, const int* in_sizes, int n_in,
                              void* d_out, int out_size) {
    const float* x    = (const float*)d_in[0];
    const float* w    = (const float*)d_in[1];
    const float* bias = (const float*)d_in[2];
    const float* mask = (const float*)d_in[3];

    const int nx4 = (MDIM * KDIM) / 4;   // 8388608
    const int nw4 = (NDIM * KDIM) / 4;   // 1048576
    split_x_kernel<<<(nx4 + 255) / 256, 256>>>((const float4*)x, nx4);
    split_w_kernel<<<(nw4 + 255) / 256, 256>>>((const float4*)w, (const float4*)mask, nw4);

    cudaFuncSetAttribute(gemm_fp16_kernel,
                         cudaFuncAttributeMaxDynamicSharedMemorySize, SMEM_TOTAL);
    dim3 grid(NDIM / BN, MDIM / BM);   // (16, 128)
    gemm_fp16_kernel<<<grid, 256, SMEM_TOTAL>>>((float*)d_out, bias);
}